// round 1
// baseline (speedup 1.0000x reference)
#include <cuda_runtime.h>
#include <cuda_bf16.h>
#include <math.h>

// Problem constants
#define BB 2
#define TT 2048
#define DM 1024
#define NH 16
#define HSZ 64
#define MROWS (BB*TT)          // 4096
#define BH (BB*NH)             // 32
#define NCH 16                 // chunks along T
#define CS (TT/NCH)            // 128 steps per chunk

// ---------------- scratch (device globals; no allocations allowed) ----------
__device__ float g_qkv[(size_t)MROWS * 3 * DM];        // [4096, 3072]
__device__ float g_qs[(size_t)BH * TT * HSZ];          // softmax(q)*Hs^-0.5, [bh,t,c]
__device__ float g_ke[(size_t)BH * TT * HSZ];          // exp(k - kmax), [bh,t,c]
__device__ float g_zc[(size_t)BH * TT * HSZ];          // cumsum_t ke, [bh,t,c]
__device__ float g_Sch[(size_t)BH * NCH * HSZ * HSZ];  // per-chunk state totals
__device__ float g_Spre[(size_t)BH * NCH * HSZ * HSZ]; // exclusive prefix states
__device__ float g_xo[(size_t)MROWS * DM];             // [4096, 1024]

// ---------------- K1/K6: SGEMM C[M,N] = A[M,K] @ B[N,K]^T (all row-major) ---
// BM=BN=128, BK=8, 256 threads, 8x8 microtile.
__global__ __launch_bounds__(256) void sgemm_nt(const float* __restrict__ A,
                                                const float* __restrict__ B,
                                                float* __restrict__ C,
                                                int M, int N, int K) {
    __shared__ float As[8][132];
    __shared__ float Bs[8][132];
    const int tid = threadIdx.x;
    const int bm = blockIdx.y * 128;
    const int bn = blockIdx.x * 128;
    const int lr = tid >> 1;            // 0..127: tile row
    const int lk = (tid & 1) * 4;       // 0 or 4: k offset
    const int tr = (tid >> 4) * 8;      // 0..120
    const int tc = (tid & 15) * 8;      // 0..120

    float acc[8][8];
    #pragma unroll
    for (int i = 0; i < 8; i++)
        #pragma unroll
        for (int j = 0; j < 8; j++) acc[i][j] = 0.f;

    for (int k0 = 0; k0 < K; k0 += 8) {
        float4 av = *(const float4*)&A[(size_t)(bm + lr) * K + k0 + lk];
        float4 bv = *(const float4*)&B[(size_t)(bn + lr) * K + k0 + lk];
        __syncthreads();
        As[lk + 0][lr] = av.x; As[lk + 1][lr] = av.y;
        As[lk + 2][lr] = av.z; As[lk + 3][lr] = av.w;
        Bs[lk + 0][lr] = bv.x; Bs[lk + 1][lr] = bv.y;
        Bs[lk + 2][lr] = bv.z; Bs[lk + 3][lr] = bv.w;
        __syncthreads();
        #pragma unroll
        for (int kk = 0; kk < 8; kk++) {
            float4 a0 = *(const float4*)&As[kk][tr];
            float4 a1 = *(const float4*)&As[kk][tr + 4];
            float4 b0 = *(const float4*)&Bs[kk][tc];
            float4 b1 = *(const float4*)&Bs[kk][tc + 4];
            float a[8] = {a0.x, a0.y, a0.z, a0.w, a1.x, a1.y, a1.z, a1.w};
            float b[8] = {b0.x, b0.y, b0.z, b0.w, b1.x, b1.y, b1.z, b1.w};
            #pragma unroll
            for (int i = 0; i < 8; i++)
                #pragma unroll
                for (int j = 0; j < 8; j++) acc[i][j] = fmaf(a[i], b[j], acc[i][j]);
        }
    }
    #pragma unroll
    for (int i = 0; i < 8; i++) {
        float4 c0 = {acc[i][0], acc[i][1], acc[i][2], acc[i][3]};
        float4 c1 = {acc[i][4], acc[i][5], acc[i][6], acc[i][7]};
        *(float4*)&C[(size_t)(bm + tr + i) * N + bn + tc]     = c0;
        *(float4*)&C[(size_t)(bm + tr + i) * N + bn + tc + 4] = c1;
    }
}

// ---------------- K2a: row softmax of q (one warp per (bh,t) row) -----------
__global__ __launch_bounds__(256) void softmax_q_kernel(const float* __restrict__ qkv,
                                                        float* __restrict__ qs) {
    int warp = (blockIdx.x * blockDim.x + threadIdx.x) >> 5;
    int lane = threadIdx.x & 31;
    if (warp >= BH * TT) return;
    int bh = warp / TT, t = warp % TT;
    int b = bh / NH, h = bh % NH;
    const float* row = qkv + ((size_t)(b * TT + t)) * (3 * DM) + h * HSZ;
    float v0 = row[lane], v1 = row[lane + 32];
    float m = fmaxf(v0, v1);
    #pragma unroll
    for (int o = 16; o; o >>= 1) m = fmaxf(m, __shfl_xor_sync(0xFFFFFFFFu, m, o));
    float e0 = expf(v0 - m), e1 = expf(v1 - m);
    float s = e0 + e1;
    #pragma unroll
    for (int o = 16; o; o >>= 1) s += __shfl_xor_sync(0xFFFFFFFFu, s, o);
    float inv = 0.125f / s;  // * Hs^-0.5
    float* out = qs + ((size_t)bh * TT + t) * HSZ;
    out[lane] = e0 * inv;
    out[lane + 32] = e1 * inv;
}

// ---------------- K2b: per-(b,h) kmax, k_exp, cumsum z ----------------------
__global__ __launch_bounds__(256) void k_stats_kernel(const float* __restrict__ qkv,
                                                      float* __restrict__ ke,
                                                      float* __restrict__ zc) {
    int bh = blockIdx.x;
    int b = bh / NH, h = bh % NH;
    int c = threadIdx.x & 63;
    int j = threadIdx.x >> 6;                 // 0..3: T quarter
    const int Q = TT / 4;                     // 512
    __shared__ float red[4][64];
    __shared__ float kmax_s[64];
    __shared__ float zoff_s[4][64];
    const float* kbase = qkv + (size_t)b * TT * (3 * DM) + DM + h * HSZ;

    float m = -1e30f;
    for (int t = j * Q; t < (j + 1) * Q; t++)
        m = fmaxf(m, kbase[(size_t)t * (3 * DM) + c]);
    red[j][c] = m;
    __syncthreads();
    if (j == 0)
        kmax_s[c] = fmaxf(fmaxf(red[0][c], red[1][c]), fmaxf(red[2][c], red[3][c]));
    __syncthreads();
    float km = kmax_s[c];

    float* keb = ke + (size_t)bh * TT * HSZ;
    float zs = 0.f;
    for (int t = j * Q; t < (j + 1) * Q; t++) {
        float e = expf(kbase[(size_t)t * (3 * DM) + c] - km);
        keb[(size_t)t * HSZ + c] = e;
        zs += e;
    }
    red[j][c] = zs;
    __syncthreads();
    if (j == 0) {
        float r = 0.f;
        #pragma unroll
        for (int i = 0; i < 4; i++) { zoff_s[i][c] = r; r += red[i][c]; }
    }
    __syncthreads();

    float z = zoff_s[j][c];
    float* zb = zc + (size_t)bh * TT * HSZ;
    for (int t = j * Q; t < (j + 1) * Q; t++) {
        z += keb[(size_t)t * HSZ + c];
        zb[(size_t)t * HSZ + c] = z;
    }
}

// ---------------- K3: per-chunk state totals S_chunk = ke^T @ v -------------
__global__ __launch_bounds__(256) void chunk_sums_kernel(const float* __restrict__ ke,
                                                         const float* __restrict__ qkv,
                                                         float* __restrict__ Sch) {
    int bh = blockIdx.x >> 4, ch = blockIdx.x & 15;
    int b = bh / NH, h = bh % NH;
    int tid = threadIdx.x;
    int d = tid & 63;
    int cb = (tid >> 6) * 16;
    __shared__ float keS[32][64];
    __shared__ float vS[32][64];
    float acc[16];
    #pragma unroll
    for (int i = 0; i < 16; i++) acc[i] = 0.f;

    for (int t0 = 0; t0 < CS; t0 += 32) {
        for (int i = tid; i < 32 * 64; i += 256) {
            int tt = i >> 6, cc = i & 63;
            int t = ch * CS + t0 + tt;
            keS[tt][cc] = ke[((size_t)bh * TT + t) * HSZ + cc];
            vS[tt][cc]  = qkv[((size_t)(b * TT + t)) * (3 * DM) + 2 * DM + h * HSZ + cc];
        }
        __syncthreads();
        #pragma unroll 8
        for (int tt = 0; tt < 32; tt++) {
            float vv = vS[tt][d];
            #pragma unroll
            for (int i = 0; i < 16; i++) acc[i] = fmaf(keS[tt][cb + i], vv, acc[i]);
        }
        __syncthreads();
    }
    size_t base = (size_t)blockIdx.x * (HSZ * HSZ);
    #pragma unroll
    for (int i = 0; i < 16; i++) Sch[base + (size_t)(cb + i) * HSZ + d] = acc[i];
}

// ---------------- K4: exclusive prefix of chunk states over chunks ----------
__global__ __launch_bounds__(256) void state_prefix_kernel(const float* __restrict__ Sch,
                                                           float* __restrict__ Spre) {
    int bh = blockIdx.x;
    for (int e = threadIdx.x; e < HSZ * HSZ; e += 256) {
        float run = 0.f;
        #pragma unroll
        for (int ch = 0; ch < NCH; ch++) {
            size_t idx = ((size_t)bh * NCH + ch) * (HSZ * HSZ) + e;
            Spre[idx] = run;
            run += Sch[idx];
        }
    }
}

// ---------------- K5: per-chunk scan producing xo ---------------------------
__global__ __launch_bounds__(256) void attn_scan_kernel(const float* __restrict__ qs,
                                                        const float* __restrict__ ke,
                                                        const float* __restrict__ zc,
                                                        const float* __restrict__ qkv,
                                                        const float* __restrict__ Spre,
                                                        float* __restrict__ xo) {
    int bh = blockIdx.x >> 4, ch = blockIdx.x & 15;
    int b = bh / NH, h = bh % NH;
    int tid = threadIdx.x;
    int d = tid & 63;
    int cb = (tid >> 6) * 16;

    float S[16];
    size_t sp = (size_t)blockIdx.x * (HSZ * HSZ);
    #pragma unroll
    for (int i = 0; i < 16; i++) S[i] = Spre[sp + (size_t)(cb + i) * HSZ + d];

    __shared__ float ke_s[64], v_s[64], qn_s[64];
    __shared__ float red[4][64];
    const int t0 = ch * CS;

    // prefetch step 0 (threads 0..63)
    float pke = 0.f, pqn = 0.f, pv = 0.f;
    if (tid < 64) {
        size_t r = ((size_t)bh * TT + t0) * HSZ + tid;
        pke = ke[r];
        pqn = qs[r] / (zc[r] + 1e-9f);
        pv  = qkv[((size_t)(b * TT + t0)) * (3 * DM) + 2 * DM + h * HSZ + tid];
    }

    for (int s = 0; s < CS; s++) {
        int t = t0 + s;
        if (tid < 64) {
            ke_s[tid] = pke; qn_s[tid] = pqn; v_s[tid] = pv;
            if (s + 1 < CS) {   // prefetch next step during compute
                size_t r = ((size_t)bh * TT + t + 1) * HSZ + tid;
                pke = ke[r];
                pqn = qs[r] / (zc[r] + 1e-9f);
                pv  = qkv[((size_t)(b * TT + t + 1)) * (3 * DM) + 2 * DM + h * HSZ + tid];
            }
        }
        __syncthreads();
        float vv = v_s[d];
        float p = 0.f;
        #pragma unroll
        for (int i = 0; i < 16; i++) {
            S[i] = fmaf(ke_s[cb + i], vv, S[i]);  // inclusive update
            p    = fmaf(qn_s[cb + i], S[i], p);
        }
        red[tid >> 6][d] = p;
        __syncthreads();
        if (tid < 64) {
            float o = red[0][tid] + red[1][tid] + red[2][tid] + red[3][tid];
            xo[((size_t)(b * TT + t)) * DM + h * HSZ + tid] = o;
        }
    }
}

// ---------------- launch ----------------------------------------------------
extern "C" void kernel_launch(void* const* d_in, const int* in_sizes, int n_in,
                              void* d_out, int out_size) {
    const float* x     = (const float*)d_in[0];  // [2,2048,1024]
    const float* W_qkv = (const float*)d_in[1];  // [3072,1024]
    const float* W_out = (const float*)d_in[2];  // [1024,1024]
    float* out = (float*)d_out;                  // [4096,1024]

    float *qkv, *qs, *ke, *zc, *Sch, *Spre, *xo;
    cudaGetSymbolAddress((void**)&qkv,  g_qkv);
    cudaGetSymbolAddress((void**)&qs,   g_qs);
    cudaGetSymbolAddress((void**)&ke,   g_ke);
    cudaGetSymbolAddress((void**)&zc,   g_zc);
    cudaGetSymbolAddress((void**)&Sch,  g_Sch);
    cudaGetSymbolAddress((void**)&Spre, g_Spre);
    cudaGetSymbolAddress((void**)&xo,   g_xo);

    // K1: qkv = x @ W_qkv^T   [4096,3072]
    {
        dim3 grid((3 * DM) / 128, MROWS / 128);
        sgemm_nt<<<grid, 256>>>(x, W_qkv, qkv, MROWS, 3 * DM, DM);
    }
    // K2a: softmax(q)*Hs^-0.5
    softmax_q_kernel<<<(BH * TT) / 8, 256>>>(qkv, qs);
    // K2b: kmax, k_exp, cumsum z
    k_stats_kernel<<<BH, 256>>>(qkv, ke, zc);
    // K3: per-chunk state totals
    chunk_sums_kernel<<<BH * NCH, 256>>>(ke, qkv, Sch);
    // K4: exclusive prefix over chunks
    state_prefix_kernel<<<BH, 256>>>(Sch, Spre);
    // K5: chunk scan -> xo
    attn_scan_kernel<<<BH * NCH, 256>>>(qs, ke, zc, qkv, Spre, xo);
    // K6: out = xo @ W_out^T  [4096,1024]
    {
        dim3 grid(DM / 128, MROWS / 128);
        sgemm_nt<<<grid, 256>>>(xo, W_out, out, MROWS, DM, DM);
    }
}

// round 17
// speedup vs baseline: 1.8514x; 1.8514x over previous
#include <cuda_runtime.h>
#include <cuda_bf16.h>
#include <math.h>
#include <stdint.h>

// ---------------- problem constants ----------------
#define BB 2
#define TT 2048
#define DM 1024
#define NH 16
#define HSZ 64
#define MROWS (BB*TT)          // 4096
#define BH (BB*NH)             // 32
#define NCH 16                 // chunks along T (scan)
#define CS (TT/NCH)            // 128 steps per chunk

// GEMM tiling (mma.sync path)
#define GBM 128
#define GBN 128
#define GKC 32                 // K per chunk (bf16)
#define SROW 40                // smem row stride in bf16 (80 B)
#define STAGE_BYTES (4 * 128 * SROW * 2)   // Ah|Al|Bh|Bl = 40960 B
#define OFF_AL (128 * SROW * 2)            // 10240
#define OFF_BH (2 * 128 * SROW * 2)        // 20480
#define OFF_BL (3 * 128 * SROW * 2)        // 30720
#define GEMM_SMEM_BYTES (2 * STAGE_BYTES)  // 81920

// ---------------- scratch (device globals) ----------------
__device__ float g_qkv[(size_t)MROWS * 3 * DM];
__device__ float g_qs[(size_t)BH * TT * HSZ];
__device__ float g_ke[(size_t)BH * TT * HSZ];
__device__ float g_zc[(size_t)BH * TT * HSZ];
__device__ float g_Sch[(size_t)BH * NCH * HSZ * HSZ];
__device__ float g_Spre[(size_t)BH * NCH * HSZ * HSZ];
__device__ float g_xo[(size_t)MROWS * DM];
// bf16 split operands
__device__ __nv_bfloat16 g_Ahi[(size_t)MROWS * DM];
__device__ __nv_bfloat16 g_Alo[(size_t)MROWS * DM];
__device__ __nv_bfloat16 g_Bhi[(size_t)3 * DM * DM];
__device__ __nv_bfloat16 g_Blo[(size_t)3 * DM * DM];
__device__ __nv_bfloat16 g_Whi[(size_t)DM * DM];
__device__ __nv_bfloat16 g_Wlo[(size_t)DM * DM];

// ---------------- baseline-PTX helpers (legal on sm_103 family target) ------
__device__ __forceinline__ uint32_t smem_to_u32(const void* p) {
    uint32_t a;
    asm("{ .reg .u64 t; cvta.to.shared.u64 t, %1; cvt.u32.u64 %0, t; }" : "=r"(a) : "l"(p));
    return a;
}
__device__ __forceinline__ void cpa16(uint32_t s, const void* g) {
    asm volatile("cp.async.cg.shared.global [%0], [%1], 16;" :: "r"(s), "l"(g));
}
#define CPA_COMMIT() asm volatile("cp.async.commit_group;" ::: "memory")

__device__ __forceinline__ void ldmx4(uint32_t* r, uint32_t addr) {
    asm volatile("ldmatrix.sync.aligned.m8n8.x4.shared.b16 {%0,%1,%2,%3}, [%4];"
                 : "=r"(r[0]), "=r"(r[1]), "=r"(r[2]), "=r"(r[3]) : "r"(addr));
}
__device__ __forceinline__ void ldmx2(uint32_t& r0, uint32_t& r1, uint32_t addr) {
    asm volatile("ldmatrix.sync.aligned.m8n8.x2.shared.b16 {%0,%1}, [%2];"
                 : "=r"(r0), "=r"(r1) : "r"(addr));
}
__device__ __forceinline__ void mma_bf16(float* c, const uint32_t* a, uint32_t b0, uint32_t b1) {
    asm volatile("mma.sync.aligned.m16n8k16.row.col.f32.bf16.bf16.f32 "
                 "{%0,%1,%2,%3}, {%4,%5,%6,%7}, {%8,%9}, {%0,%1,%2,%3};"
                 : "+f"(c[0]), "+f"(c[1]), "+f"(c[2]), "+f"(c[3])
                 : "r"(a[0]), "r"(a[1]), "r"(a[2]), "r"(a[3]), "r"(b0), "r"(b1));
}

// ---------------- split conversion: fp32 -> bf16 hi + bf16 lo ----------------
__device__ __forceinline__ uint32_t pack2bf(__nv_bfloat16 a, __nv_bfloat16 b) {
    return (uint32_t)__bfloat16_as_ushort(a) | ((uint32_t)__bfloat16_as_ushort(b) << 16);
}
__global__ __launch_bounds__(256) void cvt_split4(const float4* __restrict__ X,
                                                  uint2* __restrict__ hi,
                                                  uint2* __restrict__ lo, int n4) {
    int i = blockIdx.x * 256 + threadIdx.x;
    if (i >= n4) return;
    float4 v = X[i];
    __nv_bfloat16 h0 = __float2bfloat16(v.x), h1 = __float2bfloat16(v.y);
    __nv_bfloat16 h2 = __float2bfloat16(v.z), h3 = __float2bfloat16(v.w);
    __nv_bfloat16 l0 = __float2bfloat16(v.x - __bfloat162float(h0));
    __nv_bfloat16 l1 = __float2bfloat16(v.y - __bfloat162float(h1));
    __nv_bfloat16 l2 = __float2bfloat16(v.z - __bfloat162float(h2));
    __nv_bfloat16 l3 = __float2bfloat16(v.w - __bfloat162float(h3));
    hi[i] = make_uint2(pack2bf(h0, h1), pack2bf(h2, h3));
    lo[i] = make_uint2(pack2bf(l0, l1), pack2bf(l2, l3));
}

// ---------------- bf16x3 GEMM via mma.sync: C[M,N] = A[M,K] @ B[N,K]^T -------
// 128x128 block, 8 warps (warp tile 32x64), K-chunk 32, double-buffered cp.async.
__global__ __launch_bounds__(256) void gemm_bf16x3_mma(
    const __nv_bfloat16* __restrict__ Ahi, const __nv_bfloat16* __restrict__ Alo,
    const __nv_bfloat16* __restrict__ Bhi, const __nv_bfloat16* __restrict__ Blo,
    float* __restrict__ C, int M, int N, int K) {
    extern __shared__ char smem[];
    const uint32_t sb = smem_to_u32(smem);
    const int tid = threadIdx.x;
    const int lane = tid & 31, wid = tid >> 5;
    const int warp_m = wid & 3, warp_n = wid >> 2;
    const int bm = blockIdx.y * GBM, bn = blockIdx.x * GBN;
    const int m0 = warp_m * 32, n0 = warp_n * 64;

    float acc[2][8][4];
    #pragma unroll
    for (int i = 0; i < 2; i++)
        #pragma unroll
        for (int j = 0; j < 8; j++)
            #pragma unroll
            for (int q = 0; q < 4; q++) acc[i][j][q] = 0.f;

    const int nch = K / GKC;

    // issue chunk 0
    {
        #pragma unroll
        for (int i = 0; i < 2; i++) {
            int idx = tid + i * 256;
            int row = idx >> 2, vec = idx & 3;
            uint32_t so = sb + row * (SROW * 2) + vec * 16;
            size_t ga = (size_t)(bm + row) * K + vec * 8;
            size_t gb = (size_t)(bn + row) * K + vec * 8;
            cpa16(so,          Ahi + ga);
            cpa16(so + OFF_AL, Alo + ga);
            cpa16(so + OFF_BH, Bhi + gb);
            cpa16(so + OFF_BL, Blo + gb);
        }
        CPA_COMMIT();
    }

    const int r15 = lane & 15;
    const int akh = (lane >> 4) * 8;          // A: k half select
    const int b7 = lane & 7;
    const int bkh = ((lane >> 3) & 1) * 8;    // B: k half select

    for (int kc = 0; kc < nch; kc++) {
        // issue chunk kc+1 into the other stage
        if (kc + 1 < nch) {
            uint32_t st = sb + ((kc + 1) & 1) * STAGE_BYTES;
            int k0 = (kc + 1) * GKC;
            #pragma unroll
            for (int i = 0; i < 2; i++) {
                int idx = tid + i * 256;
                int row = idx >> 2, vec = idx & 3;
                uint32_t so = st + row * (SROW * 2) + vec * 16;
                size_t ga = (size_t)(bm + row) * K + k0 + vec * 8;
                size_t gb = (size_t)(bn + row) * K + k0 + vec * 8;
                cpa16(so,          Ahi + ga);
                cpa16(so + OFF_AL, Alo + ga);
                cpa16(so + OFF_BH, Bhi + gb);
                cpa16(so + OFF_BL, Blo + gb);
            }
            CPA_COMMIT();
            asm volatile("cp.async.wait_group 1;" ::: "memory");
        } else {
            asm volatile("cp.async.wait_group 0;" ::: "memory");
        }
        __syncthreads();

        const uint32_t st = sb + (kc & 1) * STAGE_BYTES;
        #pragma unroll
        for (int ks = 0; ks < 2; ks++) {      // two k16 steps per chunk
            const int kk = ks * 16;
            uint32_t ah[2][4], al[2][4];
            #pragma unroll
            for (int mt = 0; mt < 2; mt++) {
                uint32_t aaddr = st + (uint32_t)(m0 + mt * 16 + r15) * (SROW * 2)
                               + (uint32_t)(kk + akh) * 2;
                ldmx4(ah[mt], aaddr);
                ldmx4(al[mt], aaddr + OFF_AL);
            }
            #pragma unroll
            for (int nt = 0; nt < 8; nt++) {
                uint32_t baddr = st + OFF_BH + (uint32_t)(n0 + nt * 8 + b7) * (SROW * 2)
                               + (uint32_t)(kk + bkh) * 2;
                uint32_t bh0, bh1, bl0, bl1;
                ldmx2(bh0, bh1, baddr);
                ldmx2(bl0, bl1, baddr + OFF_AL);   // Bl is 10240 past Bh
                #pragma unroll
                for (int mt = 0; mt < 2; mt++) {
                    mma_bf16(acc[mt][nt], ah[mt], bh0, bh1);  // hi*hi
                    mma_bf16(acc[mt][nt], ah[mt], bl0, bl1);  // hi*lo
                    mma_bf16(acc[mt][nt], al[mt], bh0, bh1);  // lo*hi
                }
            }
        }
        __syncthreads();
    }

    // epilogue: c0/c1 -> (row, col..col+1); c2/c3 -> (row+8, ...)
    const int crow = lane >> 2;
    const int ccol = (lane & 3) * 2;
    #pragma unroll
    for (int mt = 0; mt < 2; mt++) {
        #pragma unroll
        for (int nt = 0; nt < 8; nt++) {
            int row = bm + m0 + mt * 16 + crow;
            int col = bn + n0 + nt * 8 + ccol;
            float2 v0 = {acc[mt][nt][0], acc[mt][nt][1]};
            float2 v1 = {acc[mt][nt][2], acc[mt][nt][3]};
            *(float2*)&C[(size_t)row * N + col] = v0;
            *(float2*)&C[(size_t)(row + 8) * N + col] = v1;
        }
    }
}

// ---------------- K2a: row softmax of q ----------------
__global__ __launch_bounds__(256) void softmax_q_kernel(const float* __restrict__ qkv,
                                                        float* __restrict__ qs) {
    int warp = (blockIdx.x * blockDim.x + threadIdx.x) >> 5;
    int lane = threadIdx.x & 31;
    if (warp >= BH * TT) return;
    int bh = warp / TT, t = warp % TT;
    int b = bh / NH, h = bh % NH;
    const float* row = qkv + ((size_t)(b * TT + t)) * (3 * DM) + h * HSZ;
    float v0 = row[lane], v1 = row[lane + 32];
    float m = fmaxf(v0, v1);
    #pragma unroll
    for (int o = 16; o; o >>= 1) m = fmaxf(m, __shfl_xor_sync(0xFFFFFFFFu, m, o));
    float e0 = expf(v0 - m), e1 = expf(v1 - m);
    float s = e0 + e1;
    #pragma unroll
    for (int o = 16; o; o >>= 1) s += __shfl_xor_sync(0xFFFFFFFFu, s, o);
    float inv = 0.125f / s;
    float* out = qs + ((size_t)bh * TT + t) * HSZ;
    out[lane] = e0 * inv;
    out[lane + 32] = e1 * inv;
}

// ---------------- K2b: per-(b,h) kmax, k_exp, cumsum z ----------------
__global__ __launch_bounds__(256) void k_stats_kernel(const float* __restrict__ qkv,
                                                      float* __restrict__ ke,
                                                      float* __restrict__ zc) {
    int bh = blockIdx.x;
    int b = bh / NH, h = bh % NH;
    int c = threadIdx.x & 63;
    int j = threadIdx.x >> 6;
    const int Q = TT / 4;
    __shared__ float red[4][64];
    __shared__ float kmax_s[64];
    __shared__ float zoff_s[4][64];
    const float* kbase = qkv + (size_t)b * TT * (3 * DM) + DM + h * HSZ;

    float m = -1e30f;
    for (int t = j * Q; t < (j + 1) * Q; t++)
        m = fmaxf(m, kbase[(size_t)t * (3 * DM) + c]);
    red[j][c] = m;
    __syncthreads();
    if (j == 0)
        kmax_s[c] = fmaxf(fmaxf(red[0][c], red[1][c]), fmaxf(red[2][c], red[3][c]));
    __syncthreads();
    float km = kmax_s[c];

    float* keb = ke + (size_t)bh * TT * HSZ;
    float zs = 0.f;
    for (int t = j * Q; t < (j + 1) * Q; t++) {
        float e = expf(kbase[(size_t)t * (3 * DM) + c] - km);
        keb[(size_t)t * HSZ + c] = e;
        zs += e;
    }
    red[j][c] = zs;
    __syncthreads();
    if (j == 0) {
        float r = 0.f;
        #pragma unroll
        for (int i = 0; i < 4; i++) { zoff_s[i][c] = r; r += red[i][c]; }
    }
    __syncthreads();

    float z = zoff_s[j][c];
    float* zb = zc + (size_t)bh * TT * HSZ;
    for (int t = j * Q; t < (j + 1) * Q; t++) {
        z += keb[(size_t)t * HSZ + c];
        zb[(size_t)t * HSZ + c] = z;
    }
}

// ---------------- K3: per-chunk state totals ----------------
__global__ __launch_bounds__(256) void chunk_sums_kernel(const float* __restrict__ ke,
                                                         const float* __restrict__ qkv,
                                                         float* __restrict__ Sch) {
    int bh = blockIdx.x >> 4, ch = blockIdx.x & 15;
    int b = bh / NH, h = bh % NH;
    int tid = threadIdx.x;
    int d = tid & 63;
    int cb = (tid >> 6) * 16;
    __shared__ float keS[32][64];
    __shared__ float vS[32][64];
    float acc[16];
    #pragma unroll
    for (int i = 0; i < 16; i++) acc[i] = 0.f;

    for (int t0 = 0; t0 < CS; t0 += 32) {
        for (int i = tid; i < 32 * 64; i += 256) {
            int tt = i >> 6, cc = i & 63;
            int t = ch * CS + t0 + tt;
            keS[tt][cc] = ke[((size_t)bh * TT + t) * HSZ + cc];
            vS[tt][cc]  = qkv[((size_t)(b * TT + t)) * (3 * DM) + 2 * DM + h * HSZ + cc];
        }
        __syncthreads();
        #pragma unroll 8
        for (int tt = 0; tt < 32; tt++) {
            float vv = vS[tt][d];
            #pragma unroll
            for (int i = 0; i < 16; i++) acc[i] = fmaf(keS[tt][cb + i], vv, acc[i]);
        }
        __syncthreads();
    }
    size_t base = (size_t)blockIdx.x * (HSZ * HSZ);
    #pragma unroll
    for (int i = 0; i < 16; i++) Sch[base + (size_t)(cb + i) * HSZ + d] = acc[i];
}

// ---------------- K4: exclusive prefix over chunks ----------------
__global__ __launch_bounds__(256) void state_prefix_kernel(const float* __restrict__ Sch,
                                                           float* __restrict__ Spre) {
    int bh = blockIdx.x;
    for (int e = threadIdx.x; e < HSZ * HSZ; e += 256) {
        float run = 0.f;
        #pragma unroll
        for (int ch = 0; ch < NCH; ch++) {
            size_t idx = ((size_t)bh * NCH + ch) * (HSZ * HSZ) + e;
            Spre[idx] = run;
            run += Sch[idx];
        }
    }
}

// ---------------- K5: per-chunk scan -> xo ----------------
__global__ __launch_bounds__(256) void attn_scan_kernel(const float* __restrict__ qs,
                                                        const float* __restrict__ ke,
                                                        const float* __restrict__ zc,
                                                        const float* __restrict__ qkv,
                                                        const float* __restrict__ Spre,
                                                        float* __restrict__ xo) {
    int bh = blockIdx.x >> 4, ch = blockIdx.x & 15;
    int b = bh / NH, h = bh % NH;
    int tid = threadIdx.x;
    int d = tid & 63;
    int cb = (tid >> 6) * 16;

    float S[16];
    size_t sp = (size_t)blockIdx.x * (HSZ * HSZ);
    #pragma unroll
    for (int i = 0; i < 16; i++) S[i] = Spre[sp + (size_t)(cb + i) * HSZ + d];

    __shared__ float ke_s[64], v_s[64], qn_s[64];
    __shared__ float red[4][64];
    const int t0 = ch * CS;

    float pke = 0.f, pqn = 0.f, pv = 0.f;
    if (tid < 64) {
        size_t r = ((size_t)bh * TT + t0) * HSZ + tid;
        pke = ke[r];
        pqn = qs[r] / (zc[r] + 1e-9f);
        pv  = qkv[((size_t)(b * TT + t0)) * (3 * DM) + 2 * DM + h * HSZ + tid];
    }

    for (int s = 0; s < CS; s++) {
        int t = t0 + s;
        if (tid < 64) {
            ke_s[tid] = pke; qn_s[tid] = pqn; v_s[tid] = pv;
            if (s + 1 < CS) {
                size_t r = ((size_t)bh * TT + t + 1) * HSZ + tid;
                pke = ke[r];
                pqn = qs[r] / (zc[r] + 1e-9f);
                pv  = qkv[((size_t)(b * TT + t + 1)) * (3 * DM) + 2 * DM + h * HSZ + tid];
            }
        }
        __syncthreads();
        float vv = v_s[d];
        float p = 0.f;
        #pragma unroll
        for (int i = 0; i < 16; i++) {
            S[i] = fmaf(ke_s[cb + i], vv, S[i]);
            p    = fmaf(qn_s[cb + i], S[i], p);
        }
        red[tid >> 6][d] = p;
        __syncthreads();
        if (tid < 64) {
            float o = red[0][tid] + red[1][tid] + red[2][tid] + red[3][tid];
            xo[((size_t)(b * TT + t)) * DM + h * HSZ + tid] = o;
        }
    }
}

// ---------------- launch ----------------
extern "C" void kernel_launch(void* const* d_in, const int* in_sizes, int n_in,
                              void* d_out, int out_size) {
    const float* x     = (const float*)d_in[0];
    const float* W_qkv = (const float*)d_in[1];
    const float* W_out = (const float*)d_in[2];
    float* out = (float*)d_out;

    float *qkv, *qs, *ke, *zc, *Sch, *Spre, *xo;
    __nv_bfloat16 *Ahi, *Alo, *Bhi, *Blo, *Whi, *Wlo;
    cudaGetSymbolAddress((void**)&qkv,  g_qkv);
    cudaGetSymbolAddress((void**)&qs,   g_qs);
    cudaGetSymbolAddress((void**)&ke,   g_ke);
    cudaGetSymbolAddress((void**)&zc,   g_zc);
    cudaGetSymbolAddress((void**)&Sch,  g_Sch);
    cudaGetSymbolAddress((void**)&Spre, g_Spre);
    cudaGetSymbolAddress((void**)&xo,   g_xo);
    cudaGetSymbolAddress((void**)&Ahi,  g_Ahi);
    cudaGetSymbolAddress((void**)&Alo,  g_Alo);
    cudaGetSymbolAddress((void**)&Bhi,  g_Bhi);
    cudaGetSymbolAddress((void**)&Blo,  g_Blo);
    cudaGetSymbolAddress((void**)&Whi,  g_Whi);
    cudaGetSymbolAddress((void**)&Wlo,  g_Wlo);

    cudaFuncSetAttribute(gemm_bf16x3_mma, cudaFuncAttributeMaxDynamicSharedMemorySize,
                         GEMM_SMEM_BYTES);

    // split conversions
    {
        int n4 = MROWS * DM / 4;
        cvt_split4<<<(n4 + 255) / 256, 256>>>((const float4*)x, (uint2*)Ahi, (uint2*)Alo, n4);
        int m4 = 3 * DM * DM / 4;
        cvt_split4<<<(m4 + 255) / 256, 256>>>((const float4*)W_qkv, (uint2*)Bhi, (uint2*)Blo, m4);
        int w4 = DM * DM / 4;
        cvt_split4<<<(w4 + 255) / 256, 256>>>((const float4*)W_out, (uint2*)Whi, (uint2*)Wlo, w4);
    }

    // GEMM1: qkv = x @ W_qkv^T  [4096, 3072]
    {
        dim3 grid((3 * DM) / GBN, MROWS / GBM);
        gemm_bf16x3_mma<<<grid, 256, GEMM_SMEM_BYTES>>>(Ahi, Alo, Bhi, Blo, qkv,
                                                        MROWS, 3 * DM, DM);
    }

    softmax_q_kernel<<<(BH * TT) / 8, 256>>>(qkv, qs);
    k_stats_kernel<<<BH, 256>>>(qkv, ke, zc);
    chunk_sums_kernel<<<BH * NCH, 256>>>(ke, qkv, Sch);
    state_prefix_kernel<<<BH, 256>>>(Sch, Spre);
    attn_scan_kernel<<<BH * NCH, 256>>>(qs, ke, zc, qkv, Spre, xo);

    // convert xo, then GEMM2: out = xo @ W_out^T  [4096, 1024]
    {
        int n4 = MROWS * DM / 4;
        cvt_split4<<<(n4 + 255) / 256, 256>>>((const float4*)xo, (uint2*)Ahi, (uint2*)Alo, n4);
        dim3 grid(DM / GBN, MROWS / GBM);
        gemm_bf16x3_mma<<<grid, 256, GEMM_SMEM_BYTES>>>(Ahi, Alo, Whi, Wlo, out,
                                                        MROWS, DM, DM);
    }
}